// round 1
// baseline (speedup 1.0000x reference)
#include <cuda_runtime.h>
#include <cuda_bf16.h>
#include <math.h>

#define C    24
#define HC   96
#define FT   48
#define NPOS (FT*FT)
#define P    8            // positions per block in heads kernel
#define XNORM_A 0.007843137718737125f
#define DELTA 1.8f
#define OUT_SCALE 0.02083333395421505f

// Dense head outputs needed by decode (raw logits, sigmoid applied in decode)
__device__ float g_hmhp[17 * NPOS];
__device__ float g_hm[NPOS];

// ---------------------------------------------------------------------------
// Kernel 1: dense hm_hp (17ch) and hm (1ch) heads.
// Each block: 8 consecutive positions in one row, 256 threads.
// ---------------------------------------------------------------------------
__global__ __launch_bounds__(256) void heads_kernel(
    const float* __restrict__ x,
    const float* __restrict__ w_dw0, const float* __restrict__ b_dw0,
    const float* __restrict__ w1_0,  const float* __restrict__ b1_0,
    const float* __restrict__ w2_0,  const float* __restrict__ b2_0,
    const float* __restrict__ w_dw1, const float* __restrict__ b_dw1,
    const float* __restrict__ w1_1,  const float* __restrict__ b1_1,
    const float* __restrict__ w2_1,  const float* __restrict__ b2_1)
{
    __shared__ float xs[C][3][P + 2];     // normalized input tile (zero padded)
    __shared__ float ys[2][P][28];        // depthwise outputs, padded stride
    __shared__ float zs[2][P][100];       // pw1+relu outputs, padded stride

    const int tid   = threadIdx.x;
    const int pbase = blockIdx.x * P;     // 48 % 8 == 0 -> all same row
    const int row   = pbase / FT;
    const int col0  = pbase % FT;

    // ---- stage X: load normalized 3x(P+2) neighborhood for all 24 channels
    for (int idx = tid; idx < C * 3 * (P + 2); idx += blockDim.x) {
        int c  = idx / (3 * (P + 2));
        int r  = (idx / (P + 2)) % 3;
        int cc = idx % (P + 2);
        int gi = row + r - 1;
        int gj = col0 + cc - 1;
        float v = 0.f;
        if (gi >= 0 && gi < FT && gj >= 0 && gj < FT)
            v = x[(c * FT + gi) * FT + gj] * XNORM_A - 1.0f;
        xs[c][r][cc] = v;
    }
    __syncthreads();

    // ---- stage Y: depthwise 3x3, both heads: 2*24*8 = 384 values
    for (int idx = tid; idx < 2 * C * P; idx += blockDim.x) {
        int h   = idx / (C * P);
        int rem = idx % (C * P);
        int c   = rem / P;
        int p   = rem % P;
        const float* wd = h ? w_dw1 : w_dw0;
        const float* bd = h ? b_dw1 : b_dw0;
        float acc = bd[c];
        #pragma unroll
        for (int r = 0; r < 3; r++)
            #pragma unroll
            for (int s = 0; s < 3; s++)
                acc += wd[c * 9 + r * 3 + s] * xs[c][r][p + s];
        ys[h][p][c] = acc;
    }
    __syncthreads();

    // ---- stage Z: pw1 (24->96) + bias + relu, both heads: 192 rows
    if (tid < 2 * HC) {
        int h  = tid / HC;
        int oc = tid % HC;
        const float* w1 = h ? w1_1 : w1_0;
        const float* b1 = h ? b1_1 : b1_0;
        float acc[P];
        float b = b1[oc];
        #pragma unroll
        for (int p = 0; p < P; p++) acc[p] = b;
        #pragma unroll
        for (int k = 0; k < C; k++) {
            float wv = __ldg(&w1[oc * C + k]);
            #pragma unroll
            for (int p = 0; p < P; p++) acc[p] += wv * ys[h][p][k];
        }
        #pragma unroll
        for (int p = 0; p < P; p++) zs[h][p][oc] = fmaxf(acc[p], 0.f);
    }
    __syncthreads();

    // ---- stage O: pw2, hm_hp has 17 out channels, hm has 1: (17+1)*8 = 144
    if (tid < 18 * P) {
        int combo = tid / P;
        int p     = tid % P;
        int pos   = pbase + p;
        float acc;
        if (combo < 17) {
            int oc = combo;
            acc = b2_0[oc];
            #pragma unroll 8
            for (int k = 0; k < HC; k++)
                acc += __ldg(&w2_0[oc * HC + k]) * zs[0][p][k];
            g_hmhp[oc * NPOS + pos] = acc;
        } else {
            acc = b2_1[0];
            #pragma unroll 8
            for (int k = 0; k < HC; k++)
                acc += __ldg(&w2_1[k]) * zs[1][p][k];
            g_hm[pos] = acc;
        }
    }
}

// ---------------------------------------------------------------------------
// Decode kernel: 1 block, 576 threads (18 warps).
// ---------------------------------------------------------------------------
__device__ __forceinline__ float sigmoidf_(float v) {
    return 1.0f / (1.0f + expf(-v));
}

// depthwise-3x3 at a single position/channel, with input normalization + zero pad
__device__ __forceinline__ float dw_at(const float* __restrict__ x,
                                       const float* __restrict__ wd,
                                       const float* __restrict__ bd,
                                       int c, int i, int j)
{
    float acc = bd[c];
    #pragma unroll
    for (int r = 0; r < 3; r++) {
        int gi = i + r - 1;
        if (gi < 0 || gi >= FT) continue;
        #pragma unroll
        for (int s = 0; s < 3; s++) {
            int gj = j + s - 1;
            if (gj < 0 || gj >= FT) continue;
            float xv = x[(c * FT + gi) * FT + gj] * XNORM_A - 1.0f;
            acc += wd[c * 9 + r * 3 + s] * xv;
        }
    }
    return acc;
}

__global__ __launch_bounds__(576) void decode_kernel(
    const float* __restrict__ x,
    const float* __restrict__ hps_dw_w, const float* __restrict__ hps_dw_b,
    const float* __restrict__ hps_w1,   const float* __restrict__ hps_b1,
    const float* __restrict__ hps_w2,   const float* __restrict__ hps_b2,
    const float* __restrict__ off_dw_w, const float* __restrict__ off_dw_b,
    const float* __restrict__ off_w1,   const float* __restrict__ off_b1,
    const float* __restrict__ off_w2,   const float* __restrict__ off_b2,
    float* __restrict__ out)
{
    __shared__ float s_val[18];
    __shared__ int   s_idx[18];
    __shared__ int   s_ct;
    __shared__ float s_y[C];
    __shared__ float s_z[HC];
    __shared__ float s_kcoor[17][2];
    __shared__ int   s_top[17];
    __shared__ float s_conf[17];
    __shared__ float s_yall[17][C];
    __shared__ float s_zall[17][HC];

    const int tid  = threadIdx.x;
    const int lane = tid & 31;
    const int wid  = tid >> 5;

    // ---- phase 1: center-weighted argmax of sigmoid(hm) * w2c
    {
        float bv = -1e30f; int bi = 0x7fffffff;
        for (int p = tid; p < NPOS; p += blockDim.x) {
            float sig = sigmoidf_(g_hm[p]);
            float gy = (float)(p / FT) - (FT * 0.5f);
            float gx = (float)(p % FT) - (FT * 0.5f);
            float s = sig / (sqrtf(gy * gy + gx * gx) + DELTA);
            if (s > bv || (s == bv && p < bi)) { bv = s; bi = p; }
        }
        #pragma unroll
        for (int off = 16; off; off >>= 1) {
            float ov = __shfl_down_sync(0xffffffffu, bv, off);
            int   oi = __shfl_down_sync(0xffffffffu, bi, off);
            if (ov > bv || (ov == bv && oi < bi)) { bv = ov; bi = oi; }
        }
        if (lane == 0) { s_val[wid] = bv; s_idx[wid] = bi; }
    }
    __syncthreads();
    if (tid == 0) {
        float bv = s_val[0]; int bi = s_idx[0];
        for (int w = 1; w < 18; w++) {
            if (s_val[w] > bv || (s_val[w] == bv && s_idx[w] < bi)) {
                bv = s_val[w]; bi = s_idx[w];
            }
        }
        s_ct = bi;
    }
    __syncthreads();

    const int ct  = s_ct;
    const int cty = ct / FT, ctx = ct % FT;

    // ---- phase 2: hps head at the center position only
    if (tid < C)
        s_y[tid] = dw_at(x, hps_dw_w, hps_dw_b, tid, cty, ctx);
    __syncthreads();
    if (tid < HC) {
        float a = hps_b1[tid];
        #pragma unroll
        for (int k = 0; k < C; k++) a += hps_w1[tid * C + k] * s_y[k];
        s_z[tid] = fmaxf(a, 0.f);
    }
    __syncthreads();
    if (tid < 34) {
        float a = hps_b2[tid];
        #pragma unroll 8
        for (int k = 0; k < HC; k++) a += hps_w2[tid * HC + k] * s_z[k];
        int k17 = tid >> 1, d = tid & 1;
        s_kcoor[k17][d] = a + (d ? (float)ctx : (float)cty);
    }
    __syncthreads();

    // ---- phase 3: per-keypoint distance-weighted argmax (one warp per kpt)
    if (wid < 17) {
        float ky = s_kcoor[wid][0];
        float kx = s_kcoor[wid][1];
        const float* hmap = g_hmhp + wid * NPOS;
        float bv = -1e30f; int bi = 0x7fffffff;
        for (int p = lane; p < NPOS; p += 32) {
            float sig = sigmoidf_(hmap[p]);
            float dy = (float)(p / FT) - ky;
            float dx = (float)(p % FT) - kx;
            float s = sig / (sqrtf(dy * dy + dx * dx) + DELTA);
            if (s > bv || (s == bv && p < bi)) { bv = s; bi = p; }
        }
        #pragma unroll
        for (int off = 16; off; off >>= 1) {
            float ov = __shfl_down_sync(0xffffffffu, bv, off);
            int   oi = __shfl_down_sync(0xffffffffu, bi, off);
            if (ov > bv || (ov == bv && oi < bi)) { bv = ov; bi = oi; }
        }
        if (lane == 0) {
            s_top[wid]  = bi;
            s_conf[wid] = sigmoidf_(hmap[bi]);
        }
    }
    __syncthreads();

    // ---- phase 4: hp_offset head at the 17 winning positions
    for (int idx = tid; idx < 17 * C; idx += blockDim.x) {
        int k = idx / C, c = idx % C;
        int p = s_top[k];
        s_yall[k][c] = dw_at(x, off_dw_w, off_dw_b, c, p / FT, p % FT);
    }
    __syncthreads();
    for (int idx = tid; idx < 17 * HC; idx += blockDim.x) {
        int k = idx / HC, oc = idx % HC;
        float a = off_b1[oc];
        #pragma unroll
        for (int kk = 0; kk < C; kk++) a += off_w1[oc * C + kk] * s_yall[k][kk];
        s_zall[k][oc] = fmaxf(a, 0.f);
    }
    __syncthreads();

    // ---- phase 5: outputs: [17,3] rows = (coord_y, coord_x, conf)
    if (tid < 34) {
        int k = tid >> 1, d = tid & 1;
        int oc = tid;                        // channel 2k+d == tid
        float a = off_b2[oc];
        #pragma unroll 8
        for (int kk = 0; kk < HC; kk++) a += off_w2[oc * HC + kk] * s_zall[k][kk];
        int p = s_top[k];
        float base = d ? (float)(p % FT) : (float)(p / FT);
        out[k * 3 + d] = (a + base) * OUT_SCALE;
    }
    if (tid < 17)
        out[tid * 3 + 2] = s_conf[tid];
}

// ---------------------------------------------------------------------------
extern "C" void kernel_launch(void* const* d_in, const int* in_sizes, int n_in,
                              void* d_out, int out_size)
{
    const float* x = (const float*)d_in[0];
    // HEADS dict order: hm_hp (1..6), hm (7..12), hps (13..18), hp_offset (19..24)
    heads_kernel<<<NPOS / P, 256>>>(
        x,
        (const float*)d_in[1],  (const float*)d_in[2],
        (const float*)d_in[3],  (const float*)d_in[4],
        (const float*)d_in[5],  (const float*)d_in[6],
        (const float*)d_in[7],  (const float*)d_in[8],
        (const float*)d_in[9],  (const float*)d_in[10],
        (const float*)d_in[11], (const float*)d_in[12]);

    decode_kernel<<<1, 576>>>(
        x,
        (const float*)d_in[13], (const float*)d_in[14],
        (const float*)d_in[15], (const float*)d_in[16],
        (const float*)d_in[17], (const float*)d_in[18],
        (const float*)d_in[19], (const float*)d_in[20],
        (const float*)d_in[21], (const float*)d_in[22],
        (const float*)d_in[23], (const float*)d_in[24],
        (float*)d_out);
}

// round 2
// speedup vs baseline: 2.2018x; 2.2018x over previous
#include <cuda_runtime.h>
#include <cuda_bf16.h>
#include <math.h>

#define C    24
#define HC   96
#define FT   48
#define NPOS (FT*FT)
#define P    8            // positions per block in heads kernel
#define XNORM_A 0.007843137718737125f
#define DELTA 1.8f
#define OUT_SCALE 0.02083333395421505f

// Dense head outputs needed by decode (raw logits, sigmoid applied in decode)
__device__ float g_hmhp[17 * NPOS];
__device__ float g_hm[NPOS];

// ---------------------------------------------------------------------------
// Kernel 1: dense hm_hp (17ch) and hm (1ch) heads.
// Each block: 8 consecutive positions in one row, 256 threads.
// ---------------------------------------------------------------------------
__global__ __launch_bounds__(256) void heads_kernel(
    const float* __restrict__ x,
    const float* __restrict__ w_dw0, const float* __restrict__ b_dw0,
    const float* __restrict__ w1_0,  const float* __restrict__ b1_0,
    const float* __restrict__ w2_0,  const float* __restrict__ b2_0,
    const float* __restrict__ w_dw1, const float* __restrict__ b_dw1,
    const float* __restrict__ w1_1,  const float* __restrict__ b1_1,
    const float* __restrict__ w2_1,  const float* __restrict__ b2_1)
{
    __shared__ float xs[C][3][P + 2];     // normalized input tile (zero padded)
    __shared__ float ys[2][P][28];        // depthwise outputs, padded stride
    __shared__ float zs[2][P][100];       // pw1+relu outputs, padded stride

    const int tid   = threadIdx.x;
    const int pbase = blockIdx.x * P;     // 48 % 8 == 0 -> all same row
    const int row   = pbase / FT;
    const int col0  = pbase % FT;

    // ---- stage X: load normalized 3x(P+2) neighborhood for all 24 channels
    for (int idx = tid; idx < C * 3 * (P + 2); idx += blockDim.x) {
        int c  = idx / (3 * (P + 2));
        int r  = (idx / (P + 2)) % 3;
        int cc = idx % (P + 2);
        int gi = row + r - 1;
        int gj = col0 + cc - 1;
        float v = 0.f;
        if (gi >= 0 && gi < FT && gj >= 0 && gj < FT)
            v = x[(c * FT + gi) * FT + gj] * XNORM_A - 1.0f;
        xs[c][r][cc] = v;
    }
    __syncthreads();

    // ---- stage Y: depthwise 3x3, both heads: 2*24*8 = 384 values
    for (int idx = tid; idx < 2 * C * P; idx += blockDim.x) {
        int h   = idx / (C * P);
        int rem = idx % (C * P);
        int c   = rem / P;
        int p   = rem % P;
        const float* wd = h ? w_dw1 : w_dw0;
        const float* bd = h ? b_dw1 : b_dw0;
        float acc = bd[c];
        #pragma unroll
        for (int r = 0; r < 3; r++)
            #pragma unroll
            for (int s = 0; s < 3; s++)
                acc += wd[c * 9 + r * 3 + s] * xs[c][r][p + s];
        ys[h][p][c] = acc;
    }
    __syncthreads();

    // ---- stage Z: pw1 (24->96) + bias + relu, both heads: 192 rows
    if (tid < 2 * HC) {
        int h  = tid / HC;
        int oc = tid % HC;
        const float* w1 = h ? w1_1 : w1_0;
        const float* b1 = h ? b1_1 : b1_0;
        float acc[P];
        float b = b1[oc];
        #pragma unroll
        for (int p = 0; p < P; p++) acc[p] = b;
        #pragma unroll
        for (int k = 0; k < C; k++) {
            float wv = __ldg(&w1[oc * C + k]);
            #pragma unroll
            for (int p = 0; p < P; p++) acc[p] += wv * ys[h][p][k];
        }
        #pragma unroll
        for (int p = 0; p < P; p++) zs[h][p][oc] = fmaxf(acc[p], 0.f);
    }
    __syncthreads();

    // ---- stage O: pw2, hm_hp has 17 out channels, hm has 1: (17+1)*8 = 144
    if (tid < 18 * P) {
        int combo = tid / P;
        int p     = tid % P;
        int pos   = pbase + p;
        float acc;
        if (combo < 17) {
            int oc = combo;
            acc = b2_0[oc];
            #pragma unroll 8
            for (int k = 0; k < HC; k++)
                acc += __ldg(&w2_0[oc * HC + k]) * zs[0][p][k];
            g_hmhp[oc * NPOS + pos] = acc;
        } else {
            acc = b2_1[0];
            #pragma unroll 8
            for (int k = 0; k < HC; k++)
                acc += __ldg(&w2_1[k]) * zs[1][p][k];
            g_hm[pos] = acc;
        }
    }
}

// ---------------------------------------------------------------------------
// Decode kernel: 17 blocks (one per keypoint) x 256 threads.
// Each block independently: (A) center-weighted argmax over g_hm (identical,
// deterministic in every block), (B) hps head at the center for its own
// keypoint, (C) distance-weighted argmax over its heatmap slice, (D) hp_offset
// head at the winner + output row.
// ---------------------------------------------------------------------------
__device__ __forceinline__ float fast_sig(float v) {
    return __fdividef(1.0f, 1.0f + __expf(-v));
}

// depthwise-3x3 at a single position/channel, with input normalization + zero pad
__device__ __forceinline__ float dw_at(const float* __restrict__ x,
                                       const float* __restrict__ wd,
                                       const float* __restrict__ bd,
                                       int c, int i, int j)
{
    float acc = bd[c];
    #pragma unroll
    for (int r = 0; r < 3; r++) {
        int gi = i + r - 1;
        if (gi < 0 || gi >= FT) continue;
        #pragma unroll
        for (int s = 0; s < 3; s++) {
            int gj = j + s - 1;
            if (gj < 0 || gj >= FT) continue;
            float xv = x[(c * FT + gi) * FT + gj] * XNORM_A - 1.0f;
            acc += wd[c * 9 + r * 3 + s] * xv;
        }
    }
    return acc;
}

// block-wide argmax over (bv, bi) pairs held per-thread; result in s_out[0/1]
__device__ __forceinline__ void block_argmax(float bv, int bi,
                                             float* s_v, int* s_i,
                                             int lane, int wid,
                                             float* out_v, int* out_i)
{
    #pragma unroll
    for (int off = 16; off; off >>= 1) {
        float ov = __shfl_down_sync(0xffffffffu, bv, off);
        int   oi = __shfl_down_sync(0xffffffffu, bi, off);
        if (ov > bv || (ov == bv && oi < bi)) { bv = ov; bi = oi; }
    }
    if (lane == 0) { s_v[wid] = bv; s_i[wid] = bi; }
    __syncthreads();
    if (wid == 0 && lane == 0) {
        for (int w = 1; w < 8; w++) {
            if (s_v[w] > bv || (s_v[w] == bv && s_i[w] < bi)) {
                bv = s_v[w]; bi = s_i[w];
            }
        }
        *out_v = bv; *out_i = bi;
    }
    __syncthreads();
}

__global__ __launch_bounds__(256) void decode_kernel(
    const float* __restrict__ x,
    const float* __restrict__ hps_dw_w, const float* __restrict__ hps_dw_b,
    const float* __restrict__ hps_w1,   const float* __restrict__ hps_b1,
    const float* __restrict__ hps_w2,   const float* __restrict__ hps_b2,
    const float* __restrict__ off_dw_w, const float* __restrict__ off_dw_b,
    const float* __restrict__ off_w1,   const float* __restrict__ off_b1,
    const float* __restrict__ off_w2,   const float* __restrict__ off_b2,
    float* __restrict__ out)
{
    __shared__ float s_v[8];
    __shared__ int   s_i[8];
    __shared__ float s_bestv;
    __shared__ int   s_besti;
    __shared__ float s_y[C];
    __shared__ float s_z[HC];
    __shared__ float s_kc[2];     // kpt_coor (y, x) for this keypoint

    const int k    = blockIdx.x;  // keypoint id 0..16
    const int tid  = threadIdx.x;
    const int lane = tid & 31;
    const int wid  = tid >> 5;

    // ---- A: center-weighted argmax of sigmoid(hm) * w2c (all blocks identical)
    {
        float bv = -1e30f; int bi = 0x7fffffff;
        for (int p = tid; p < NPOS; p += 256) {
            float sig = fast_sig(g_hm[p]);
            int py = p / FT;
            float gy = (float)py - (FT * 0.5f);
            float gx = (float)(p - py * FT) - (FT * 0.5f);
            float s = __fdividef(sig, sqrtf(gy * gy + gx * gx) + DELTA);
            if (s > bv || (s == bv && p < bi)) { bv = s; bi = p; }
        }
        block_argmax(bv, bi, s_v, s_i, lane, wid, &s_bestv, &s_besti);
    }
    const int ct  = s_besti;
    const int cty = ct / FT, ctx = ct % FT;

    // ---- B: hps head at the center (only channels 2k, 2k+1 needed)
    if (tid < C)
        s_y[tid] = dw_at(x, hps_dw_w, hps_dw_b, tid, cty, ctx);
    __syncthreads();
    if (tid < HC) {
        float a = hps_b1[tid];
        #pragma unroll
        for (int kk = 0; kk < C; kk++) a += hps_w1[tid * C + kk] * s_y[kk];
        s_z[tid] = fmaxf(a, 0.f);
    }
    __syncthreads();
    if (tid < 2) {
        int oc = 2 * k + tid;
        float a = hps_b2[oc];
        #pragma unroll 8
        for (int kk = 0; kk < HC; kk++) a += hps_w2[oc * HC + kk] * s_z[kk];
        s_kc[tid] = a + (tid ? (float)ctx : (float)cty);
    }
    __syncthreads();

    // ---- C: distance-weighted argmax over this keypoint's heatmap
    const float ky = s_kc[0];
    const float kx = s_kc[1];
    const float* hmap = g_hmhp + k * NPOS;
    {
        float bv = -1e30f; int bi = 0x7fffffff;
        for (int p = tid; p < NPOS; p += 256) {
            float sig = fast_sig(hmap[p]);
            int py = p / FT;
            float dy = (float)py - ky;
            float dx = (float)(p - py * FT) - kx;
            float s = __fdividef(sig, sqrtf(dy * dy + dx * dx) + DELTA);
            if (s > bv || (s == bv && p < bi)) { bv = s; bi = p; }
        }
        __syncthreads();   // s_v/s_i reuse
        block_argmax(bv, bi, s_v, s_i, lane, wid, &s_bestv, &s_besti);
    }
    const int top = s_besti;
    const int ty  = top / FT, tx = top % FT;

    // ---- D: hp_offset head at the winner (channels 2k, 2k+1) + outputs
    if (tid < C)
        s_y[tid] = dw_at(x, off_dw_w, off_dw_b, tid, ty, tx);
    __syncthreads();
    if (tid < HC) {
        float a = off_b1[tid];
        #pragma unroll
        for (int kk = 0; kk < C; kk++) a += off_w1[tid * C + kk] * s_y[kk];
        s_z[tid] = fmaxf(a, 0.f);
    }
    __syncthreads();
    if (tid < 2) {
        int oc = 2 * k + tid;
        float a = off_b2[oc];
        #pragma unroll 8
        for (int kk = 0; kk < HC; kk++) a += off_w2[oc * HC + kk] * s_z[kk];
        float base = tid ? (float)tx : (float)ty;
        out[k * 3 + tid] = (a + base) * OUT_SCALE;
    }
    if (tid == 2)   // precise sigmoid for the reported confidence
        out[k * 3 + 2] = 1.0f / (1.0f + expf(-hmap[top]));
}

// ---------------------------------------------------------------------------
extern "C" void kernel_launch(void* const* d_in, const int* in_sizes, int n_in,
                              void* d_out, int out_size)
{
    const float* x = (const float*)d_in[0];
    // HEADS dict order: hm_hp (1..6), hm (7..12), hps (13..18), hp_offset (19..24)
    heads_kernel<<<NPOS / P, 256>>>(
        x,
        (const float*)d_in[1],  (const float*)d_in[2],
        (const float*)d_in[3],  (const float*)d_in[4],
        (const float*)d_in[5],  (const float*)d_in[6],
        (const float*)d_in[7],  (const float*)d_in[8],
        (const float*)d_in[9],  (const float*)d_in[10],
        (const float*)d_in[11], (const float*)d_in[12]);

    decode_kernel<<<17, 256>>>(
        x,
        (const float*)d_in[13], (const float*)d_in[14],
        (const float*)d_in[15], (const float*)d_in[16],
        (const float*)d_in[17], (const float*)d_in[18],
        (const float*)d_in[19], (const float*)d_in[20],
        (const float*)d_in[21], (const float*)d_in[22],
        (const float*)d_in[23], (const float*)d_in[24],
        (float*)d_out);
}

// round 3
// speedup vs baseline: 2.5386x; 1.1530x over previous
#include <cuda_runtime.h>
#include <cuda_bf16.h>
#include <math.h>

#define C    24
#define HC   96
#define FT   48
#define NPOS (FT*FT)
#define P    16           // positions per block in heads kernel (144 blocks = 1 wave)
#define NBLK (NPOS / P)   // 144
#define XNORM_A 0.007843137718737125f
#define DELTA 1.8f
#define OUT_SCALE 0.02083333395421505f

// Dense head outputs needed by decode (raw logits, sigmoid applied in decode)
__device__ float g_hmhp[17 * NPOS];
__device__ float g_hm[NPOS];
// Per-block center argmax partials: key = (score_bits<<32) | (0xFFFFFFFF - pos)
__device__ unsigned long long g_part[NBLK];

__device__ __forceinline__ float fast_sig(float v) {
    return __fdividef(1.0f, 1.0f + __expf(-v));
}

// ---------------------------------------------------------------------------
// Kernel 1: dense hm_hp (17ch) and hm (1ch) heads + per-block center argmax.
// Each block: 16 consecutive positions in one row, 256 threads. 144 blocks.
// ---------------------------------------------------------------------------
__global__ __launch_bounds__(256) void heads_kernel(
    const float* __restrict__ x,
    const float* __restrict__ w_dw0, const float* __restrict__ b_dw0,
    const float* __restrict__ w1_0,  const float* __restrict__ b1_0,
    const float* __restrict__ w2_0,  const float* __restrict__ b2_0,
    const float* __restrict__ w_dw1, const float* __restrict__ b_dw1,
    const float* __restrict__ w1_1,  const float* __restrict__ b1_1,
    const float* __restrict__ w2_1,  const float* __restrict__ b2_1)
{
    __shared__ float xs[C][3][P + 2];     // normalized input tile (zero padded)
    __shared__ float ys[2][P][28];        // depthwise outputs, padded stride
    __shared__ float zs[2][P][100];       // pw1+relu outputs, padded stride
    __shared__ unsigned long long skey[P];

    const int tid   = threadIdx.x;
    const int pbase = blockIdx.x * P;     // 48 % 16 == 0 -> all same row
    const int row   = pbase / FT;
    const int col0  = pbase % FT;

    // ---- stage X: load normalized 3x(P+2) neighborhood for all 24 channels
    for (int idx = tid; idx < C * 3 * (P + 2); idx += 256) {
        int c  = idx / (3 * (P + 2));
        int r  = (idx / (P + 2)) % 3;
        int cc = idx % (P + 2);
        int gi = row + r - 1;
        int gj = col0 + cc - 1;
        float v = 0.f;
        if (gi >= 0 && gi < FT && gj >= 0 && gj < FT)
            v = x[(c * FT + gi) * FT + gj] * XNORM_A - 1.0f;
        xs[c][r][cc] = v;
    }
    __syncthreads();

    // ---- stage Y: depthwise 3x3, both heads: 2*24*16 = 768 values
    for (int idx = tid; idx < 2 * C * P; idx += 256) {
        int h   = idx / (C * P);
        int rem = idx % (C * P);
        int c   = rem / P;
        int p   = rem % P;
        const float* wd = h ? w_dw1 : w_dw0;
        const float* bd = h ? b_dw1 : b_dw0;
        float acc = bd[c];
        #pragma unroll
        for (int r = 0; r < 3; r++)
            #pragma unroll
            for (int s = 0; s < 3; s++)
                acc += wd[c * 9 + r * 3 + s] * xs[c][r][p + s];
        ys[h][p][c] = acc;
    }
    __syncthreads();

    // ---- stage Z: pw1 (24->96) + bias + relu, both heads: 192 rows
    if (tid < 2 * HC) {
        int h  = tid / HC;
        int oc = tid % HC;
        const float* w1 = h ? w1_1 : w1_0;
        const float* b1 = h ? b1_1 : b1_0;
        float acc[P];
        float b = b1[oc];
        #pragma unroll
        for (int p = 0; p < P; p++) acc[p] = b;
        #pragma unroll
        for (int k = 0; k < C; k++) {
            float wv = __ldg(&w1[oc * C + k]);
            #pragma unroll
            for (int p = 0; p < P; p++) acc[p] += wv * ys[h][p][k];
        }
        #pragma unroll
        for (int p = 0; p < P; p++) zs[h][p][oc] = fmaxf(acc[p], 0.f);
    }
    __syncthreads();

    // ---- stage O: pw2. hm_hp 17ch + hm 1ch: 18*16 = 288 items
    for (int idx = tid; idx < 18 * P; idx += 256) {
        int combo = idx / P;
        int p     = idx % P;
        int pos   = pbase + p;
        if (combo < 17) {
            int oc = combo;
            float acc = b2_0[oc];
            #pragma unroll 8
            for (int k = 0; k < HC; k++)
                acc += __ldg(&w2_0[oc * HC + k]) * zs[0][p][k];
            g_hmhp[oc * NPOS + pos] = acc;
        } else {
            float acc = b2_1[0];
            #pragma unroll 8
            for (int k = 0; k < HC; k++)
                acc += __ldg(&w2_1[k]) * zs[1][p][k];
            g_hm[pos] = acc;
            // center score for this position
            float sig = fast_sig(acc);
            float gy = (float)row - (FT * 0.5f);
            float gx = (float)(col0 + p) - (FT * 0.5f);
            float s = __fdividef(sig, sqrtf(gy * gy + gx * gx) + DELTA);
            skey[p] = ((unsigned long long)__float_as_uint(s) << 32)
                    | (unsigned long long)(0xFFFFFFFFu - (unsigned)pos);
        }
    }
    __syncthreads();
    if (tid == 0) {
        unsigned long long best = skey[0];
        #pragma unroll
        for (int p = 1; p < P; p++) if (skey[p] > best) best = skey[p];
        g_part[blockIdx.x] = best;
    }
}

// ---------------------------------------------------------------------------
// Decode kernel: 17 blocks (one per keypoint) x 256 threads.
// ---------------------------------------------------------------------------

// depthwise-3x3 at a single position/channel, with input normalization + zero pad
__device__ __forceinline__ float dw_at(const float* __restrict__ x,
                                       const float* __restrict__ wd,
                                       const float* __restrict__ bd,
                                       int c, int i, int j)
{
    float acc = bd[c];
    #pragma unroll
    for (int r = 0; r < 3; r++) {
        int gi = i + r - 1;
        if (gi < 0 || gi >= FT) continue;
        #pragma unroll
        for (int s = 0; s < 3; s++) {
            int gj = j + s - 1;
            if (gj < 0 || gj >= FT) continue;
            float xv = x[(c * FT + gi) * FT + gj] * XNORM_A - 1.0f;
            acc += wd[c * 9 + r * 3 + s] * xv;
        }
    }
    return acc;
}

__global__ __launch_bounds__(256) void decode_kernel(
    const float* __restrict__ x,
    const float* __restrict__ hps_dw_w, const float* __restrict__ hps_dw_b,
    const float* __restrict__ hps_w1,   const float* __restrict__ hps_b1,
    const float* __restrict__ hps_w2,   const float* __restrict__ hps_b2,
    const float* __restrict__ off_dw_w, const float* __restrict__ off_dw_b,
    const float* __restrict__ off_w1,   const float* __restrict__ off_b1,
    const float* __restrict__ off_w2,   const float* __restrict__ off_b2,
    float* __restrict__ out)
{
    __shared__ unsigned long long s_k[8];
    __shared__ float s_v[8];
    __shared__ int   s_i[8];
    __shared__ int   s_ct;
    __shared__ int   s_top;
    __shared__ float s_y[C];
    __shared__ float s_z[HC];
    __shared__ float s_kc[2];     // kpt_coor (y, x) for this keypoint

    const int k    = blockIdx.x;  // keypoint id 0..16
    const int tid  = threadIdx.x;
    const int lane = tid & 31;
    const int wid  = tid >> 5;

    // ---- A': reduce the 144 per-block center keys
    {
        unsigned long long key = (tid < NBLK) ? g_part[tid] : 0ULL;
        #pragma unroll
        for (int off = 16; off; off >>= 1) {
            unsigned long long o = __shfl_down_sync(0xffffffffu, key, off);
            if (o > key) key = o;
        }
        if (lane == 0) s_k[wid] = key;
        __syncthreads();
        if (tid == 0) {
            unsigned long long best = s_k[0];
            #pragma unroll
            for (int w = 1; w < 8; w++) if (s_k[w] > best) best = s_k[w];
            s_ct = (int)(0xFFFFFFFFu - (unsigned)(best & 0xFFFFFFFFu));
        }
        __syncthreads();
    }
    const int ct  = s_ct;
    const int cty = ct / FT, ctx = ct % FT;

    // ---- B: hps head at the center (only channels 2k, 2k+1 needed)
    if (tid < C)
        s_y[tid] = dw_at(x, hps_dw_w, hps_dw_b, tid, cty, ctx);
    __syncthreads();
    if (tid < HC) {
        float a = hps_b1[tid];
        #pragma unroll
        for (int kk = 0; kk < C; kk++) a += __ldg(&hps_w1[tid * C + kk]) * s_y[kk];
        s_z[tid] = fmaxf(a, 0.f);
    }
    __syncthreads();
    // pw2 channels 2k (warp 0) and 2k+1 (warp 1), lane-parallel over HC
    if (wid < 2) {
        int oc = 2 * k + wid;
        float a = __ldg(&hps_w2[oc * HC + lane])      * s_z[lane]
                + __ldg(&hps_w2[oc * HC + lane + 32]) * s_z[lane + 32]
                + __ldg(&hps_w2[oc * HC + lane + 64]) * s_z[lane + 64];
        #pragma unroll
        for (int off = 16; off; off >>= 1)
            a += __shfl_down_sync(0xffffffffu, a, off);
        if (lane == 0)
            s_kc[wid] = a + hps_b2[oc] + (wid ? (float)ctx : (float)cty);
    }
    __syncthreads();

    // ---- C: distance-weighted argmax over this keypoint's heatmap
    const float ky = s_kc[0];
    const float kx = s_kc[1];
    const float* hmap = g_hmhp + k * NPOS;
    {
        float bv = -1e30f; int bi = 0x7fffffff;
        #pragma unroll
        for (int i = 0; i < NPOS / 256; i++) {
            int p = tid + i * 256;
            float sig = fast_sig(__ldg(&hmap[p]));
            int py = p / FT;
            float dy = (float)py - ky;
            float dx = (float)(p - py * FT) - kx;
            float s = __fdividef(sig, sqrtf(dy * dy + dx * dx) + DELTA);
            if (s > bv || (s == bv && p < bi)) { bv = s; bi = p; }
        }
        #pragma unroll
        for (int off = 16; off; off >>= 1) {
            float ov = __shfl_down_sync(0xffffffffu, bv, off);
            int   oi = __shfl_down_sync(0xffffffffu, bi, off);
            if (ov > bv || (ov == bv && oi < bi)) { bv = ov; bi = oi; }
        }
        if (lane == 0) { s_v[wid] = bv; s_i[wid] = bi; }
        __syncthreads();
        if (tid == 0) {
            float xv = s_v[0]; int xi = s_i[0];
            #pragma unroll
            for (int w = 1; w < 8; w++) {
                if (s_v[w] > xv || (s_v[w] == xv && s_i[w] < xi)) {
                    xv = s_v[w]; xi = s_i[w];
                }
            }
            s_top = xi;
        }
        __syncthreads();
    }
    const int top = s_top;
    const int ty  = top / FT, tx = top % FT;

    // ---- D: hp_offset head at the winner (channels 2k, 2k+1) + outputs
    if (tid < C)
        s_y[tid] = dw_at(x, off_dw_w, off_dw_b, tid, ty, tx);
    __syncthreads();
    if (tid < HC) {
        float a = off_b1[tid];
        #pragma unroll
        for (int kk = 0; kk < C; kk++) a += __ldg(&off_w1[tid * C + kk]) * s_y[kk];
        s_z[tid] = fmaxf(a, 0.f);
    }
    __syncthreads();
    if (wid < 2) {
        int oc = 2 * k + wid;
        float a = __ldg(&off_w2[oc * HC + lane])      * s_z[lane]
                + __ldg(&off_w2[oc * HC + lane + 32]) * s_z[lane + 32]
                + __ldg(&off_w2[oc * HC + lane + 64]) * s_z[lane + 64];
        #pragma unroll
        for (int off = 16; off; off >>= 1)
            a += __shfl_down_sync(0xffffffffu, a, off);
        if (lane == 0) {
            float base = wid ? (float)tx : (float)ty;
            out[k * 3 + wid] = (a + off_b2[oc] + base) * OUT_SCALE;
        }
    }
    if (tid == 64)   // precise sigmoid for the reported confidence
        out[k * 3 + 2] = 1.0f / (1.0f + expf(-hmap[top]));
}

// ---------------------------------------------------------------------------
extern "C" void kernel_launch(void* const* d_in, const int* in_sizes, int n_in,
                              void* d_out, int out_size)
{
    const float* x = (const float*)d_in[0];
    // HEADS dict order: hm_hp (1..6), hm (7..12), hps (13..18), hp_offset (19..24)
    heads_kernel<<<NBLK, 256>>>(
        x,
        (const float*)d_in[1],  (const float*)d_in[2],
        (const float*)d_in[3],  (const float*)d_in[4],
        (const float*)d_in[5],  (const float*)d_in[6],
        (const float*)d_in[7],  (const float*)d_in[8],
        (const float*)d_in[9],  (const float*)d_in[10],
        (const float*)d_in[11], (const float*)d_in[12]);

    decode_kernel<<<17, 256>>>(
        x,
        (const float*)d_in[13], (const float*)d_in[14],
        (const float*)d_in[15], (const float*)d_in[16],
        (const float*)d_in[17], (const float*)d_in[18],
        (const float*)d_in[19], (const float*)d_in[20],
        (const float*)d_in[21], (const float*)d_in[22],
        (const float*)d_in[23], (const float*)d_in[24],
        (float*)d_out);
}